// round 15
// baseline (speedup 1.0000x reference)
#include <cuda_runtime.h>
#include <cstdint>

#define BATCH 32
#define CIN   256
#define COUT  256
#define HH_   56
#define WW_   56
#define HW_   (HH_*WW_)
#define NPOS  (BATCH*HW_)

// ---------------- device scratch ----------------
__device__ uint4 g_xpack[NPOS * 2];        // [pos][2]: 8 u32 sign bits (bit=1 iff x>=0)
__device__ uint4 g_wpack[COUT * 9 * 2];    // [cout*9+tap][2]

// ---------------- fused pack kernel ----------------
__global__ void pack_all_kernel(const float* __restrict__ x,
                                const float* __restrict__ wgt) {
    if (blockIdx.x < 392) {                       // 392*256 == NPOS exactly
        int pos = blockIdx.x * 256 + threadIdx.x;
        int b  = pos / HW_;
        int hw = pos - b * HW_;
        const float* xp = x + (size_t)b * CIN * HW_ + hw;
        uint32_t wds[8];
        #pragma unroll
        for (int k = 0; k < 8; ++k) {
            uint32_t wd = 0;
            #pragma unroll
            for (int i = 0; i < 32; ++i) {
                float v = xp[(size_t)(k * 32 + i) * HW_];
                wd |= (v >= 0.0f ? 1u : 0u) << i;
            }
            wds[k] = wd;
        }
        g_xpack[pos * 2 + 0] = make_uint4(wds[0], wds[1], wds[2], wds[3]);
        g_xpack[pos * 2 + 1] = make_uint4(wds[4], wds[5], wds[6], wds[7]);
    } else {
        int idx = (blockIdx.x - 392) * 256 + threadIdx.x;   // cout*9+tap
        if (idx >= COUT * 9) return;
        int cout = idx / 9;
        int tap  = idx - cout * 9;
        const float* wp = wgt + (size_t)cout * CIN * 9 + tap;
        uint32_t wds[8];
        #pragma unroll
        for (int k = 0; k < 8; ++k) {
            uint32_t wd = 0;
            #pragma unroll
            for (int i = 0; i < 32; ++i) {
                float v = wp[(size_t)(k * 32 + i) * 9];
                wd |= (v >= 0.0f ? 1u : 0u) << i;
            }
            wds[k] = wd;
        }
        g_wpack[idx * 2 + 0] = make_uint4(wds[0], wds[1], wds[2], wds[3]);
        g_wpack[idx * 2 + 1] = make_uint4(wds[4], wds[5], wds[6], wds[7]);
    }
}

// ---------------- main conv: no split, no shfl, dual column streams ----------
// Block = 256 threads = 8 warps. lane = cout within warp group:
//   cout = wid*32 + lane; full 256 channels per lane (72 weight regs).
// Per thread: stream L covers w=0..27 (x cols 0..28),
//             stream R covers w=28..55 (x cols 27..55).
__global__ void __launch_bounds__(256, 2)
bconv_pop_kernel(const float* __restrict__ bias, float* __restrict__ out) {
    __shared__ uint4 xs[3 * WW_ * 2];     // [row][v][half]

    const int tid  = threadIdx.x;
    const int lane = tid & 31;
    const int wid  = tid >> 5;
    const int h    = blockIdx.x;
    const int b    = blockIdx.y;
    const int cout = wid * 32 + lane;

    const bool rv0 = (h > 0), rv2 = (h < HH_ - 1);

    // ---- stage x (3 rows x 56 cols x 32B), zero-fill invalid rows ----
    for (int i = tid; i < 3 * WW_ * 2; i += 256) {
        int row = i / (WW_ * 2);
        int rem = i - row * (WW_ * 2);
        int v = rem >> 1, j = rem & 1;
        int rin = h - 1 + row;
        uint4 val = make_uint4(0u, 0u, 0u, 0u);
        if (rin >= 0 && rin < HH_)
            val = g_xpack[((size_t)(b * HH_ + rin) * WW_ + v) * 2 + j];
        xs[(row * WW_ + v) * 2 + j] = val;
    }

    // ---- full weights in registers (72 regs) ----
    uint32_t wreg[9][8];
    #pragma unroll
    for (int t = 0; t < 9; ++t) {
        uint4 a = g_wpack[(cout * 9 + t) * 2 + 0];
        uint4 q = g_wpack[(cout * 9 + t) * 2 + 1];
        wreg[t][0] = a.x; wreg[t][1] = a.y; wreg[t][2] = a.z; wreg[t][3] = a.w;
        wreg[t][4] = q.x; wreg[t][5] = q.y; wreg[t][6] = q.z; wreg[t][7] = q.w;
    }
    const float bv = bias[cout];

    // ---- row-pad correction constants ----
    int pm[3], pl[3], pr[3];
    #pragma unroll
    for (int dh = 0; dh < 3; ++dh) {
        int p0 = 0, p1 = 0, p2 = 0;
        #pragma unroll
        for (int k = 0; k < 8; ++k) {
            p0 += __popc(wreg[dh * 3 + 0][k]);
            p1 += __popc(wreg[dh * 3 + 1][k]);
            p2 += __popc(wreg[dh * 3 + 2][k]);
        }
        pm[dh] = p0 + p1 + p2; pl[dh] = p1 + p2; pr[dh] = p0 + p1;
    }
    const int nrows = (int)rv0 + 1 + (int)rv2;
    const int cmid   = 768 * nrows + 2 * ((rv0 ? 0 : pm[0]) + (rv2 ? 0 : pm[2]));
    const int cleft  = 512 * nrows + 2 * ((rv0 ? 0 : pl[0]) + (rv2 ? 0 : pl[2]));
    const int cright = 512 * nrows + 2 * ((rv0 ? 0 : pr[0]) + (rv2 ? 0 : pr[2]));

    __syncthreads();

    float* obase = out + ((size_t)(b * COUT + cout) * HH_ + h) * WW_;

    // full 9-tap step at x column vv into ring rg (u compile-time)
    #define STEP(rg, vv, u) do {                                                \
        uint32_t xw[8];                                                         \
        int addn = 0, addm = 0, addo = 0;                                       \
        _Pragma("unroll")                                                       \
        for (int row = 0; row < 3; ++row) {                                     \
            uint4 xa = xs[(row * WW_ + (vv)) * 2 + 0];                          \
            uint4 xb = xs[(row * WW_ + (vv)) * 2 + 1];                          \
            xw[0] = xa.x; xw[1] = xa.y; xw[2] = xa.z; xw[3] = xa.w;             \
            xw[4] = xb.x; xw[5] = xb.y; xw[6] = xb.z; xw[7] = xb.w;             \
            _Pragma("unroll")                                                   \
            for (int k = 0; k < 8; ++k) {                                       \
                addn += __popc(xw[k] ^ wreg[row * 3 + 0][k]);                   \
                addm += __popc(xw[k] ^ wreg[row * 3 + 1][k]);                   \
                addo += __popc(xw[k] ^ wreg[row * 3 + 2][k]);                   \
            }                                                                   \
        }                                                                       \
        rg[((u) + 1) & 3] += addn;                                              \
        rg[(u) & 3]       += addm;                                              \
        rg[((u) + 3) & 3] += addo;                                              \
    } while (0)

    int ringL[4] = {0, 0, 0, 0};
    int ringR[4] = {0, 0, 0, 0};

    // R prefix: x col 27, dw=0 -> output w=28 (lands in slot 0)
    {
        int a = 0;
        #pragma unroll
        for (int row = 0; row < 3; ++row) {
            uint4 xa = xs[(row * WW_ + 27) * 2 + 0];
            uint4 xb = xs[(row * WW_ + 27) * 2 + 1];
            uint32_t xw[8] = {xa.x, xa.y, xa.z, xa.w, xb.x, xb.y, xb.z, xb.w};
            #pragma unroll
            for (int k = 0; k < 8; ++k)
                a += __popc(xw[k] ^ wreg[row * 3 + 0][k]);
        }
        ringR[0] = a;
    }

    for (int i0 = 0; i0 < 7; ++i0) {
        #pragma unroll
        for (int u = 0; u < 4; ++u) {
            const int i = i0 * 4 + u;      // L: v=i ; R: v=28+i
            STEP(ringL, i, u);
            STEP(ringR, 28 + i, u);

            const int slot = (u + 3) & 3;
            if (u == 0 && i0 == 0) {
                ringL[3] = 0;              // w=-1 garbage
                ringR[3] = 0;              // w=27 belongs to L
            } else {
                // L completes w = i-1 ; R completes w = 27+i
                const int cL = (i == 1) ? cleft : cmid;
                int combL = cL - 2 * ringL[slot];
                int combR = cmid - 2 * ringR[slot];
                ringL[slot] = 0;
                ringR[slot] = 0;
                obase[i - 1]  = (float)combL + bv;
                obase[27 + i] = (float)combR + bv;
            }
        }
    }

    // L postfix: w=27 still needs x col 28, dw=2 (slot 3)
    {
        int a = 0;
        #pragma unroll
        for (int row = 0; row < 3; ++row) {
            uint4 xa = xs[(row * WW_ + 28) * 2 + 0];
            uint4 xb = xs[(row * WW_ + 28) * 2 + 1];
            uint32_t xw[8] = {xa.x, xa.y, xa.z, xa.w, xb.x, xb.y, xb.z, xb.w};
            #pragma unroll
            for (int k = 0; k < 8; ++k)
                a += __popc(xw[k] ^ wreg[row * 3 + 2][k]);
        }
        ringL[3] += a;
        obase[27] = (float)(cmid - 2 * ringL[3]) + bv;
    }
    // R tail: w=55 (edge) sits in slot 3
    obase[55] = (float)(cright - 2 * ringR[3]) + bv;

    #undef STEP
}

// ---------------------------------------------------------------------------
extern "C" void kernel_launch(void* const* d_in, const int* in_sizes, int n_in,
                              void* d_out, int out_size) {
    const float* x    = (const float*)d_in[0];
    const float* wgt  = (const float*)d_in[1];
    const float* bias = (const float*)d_in[2];
    float* out = (float*)d_out;

    pack_all_kernel<<<401, 256>>>(x, wgt);
    dim3 grid(HH_, BATCH);
    bconv_pop_kernel<<<grid, 256>>>(bias, out);
}

// round 16
// speedup vs baseline: 1.2757x; 1.2757x over previous
#include <cuda_runtime.h>
#include <cstdint>

#define BATCH 32
#define CIN   256
#define COUT  256
#define HH_   56
#define WW_   56
#define HW_   (HH_*WW_)
#define NPOS  (BATCH*HW_)

// ---------------- device scratch ----------------
__device__ uint4 g_xpack[NPOS * 2];        // [pos][2]: 8 u32 sign bits (bit=1 iff x>=0)
__device__ uint4 g_wpack[COUT * 9 * 2];    // [cout*9+tap][2]

// ---------------- fused pack kernel ----------------
__global__ void pack_all_kernel(const float* __restrict__ x,
                                const float* __restrict__ wgt) {
    if (blockIdx.x < 392) {                       // 392*256 == NPOS exactly
        int pos = blockIdx.x * 256 + threadIdx.x;
        int b  = pos / HW_;
        int hw = pos - b * HW_;
        const float* xp = x + (size_t)b * CIN * HW_ + hw;
        uint32_t wds[8];
        #pragma unroll
        for (int k = 0; k < 8; ++k) {
            uint32_t wd = 0;
            #pragma unroll
            for (int i = 0; i < 32; ++i) {
                float v = xp[(size_t)(k * 32 + i) * HW_];
                wd |= (v >= 0.0f ? 1u : 0u) << i;
            }
            wds[k] = wd;
        }
        g_xpack[pos * 2 + 0] = make_uint4(wds[0], wds[1], wds[2], wds[3]);
        g_xpack[pos * 2 + 1] = make_uint4(wds[4], wds[5], wds[6], wds[7]);
    } else {
        int idx = (blockIdx.x - 392) * 256 + threadIdx.x;   // cout*9+tap
        if (idx >= COUT * 9) return;
        int cout = idx / 9;
        int tap  = idx - cout * 9;
        const float* wp = wgt + (size_t)cout * CIN * 9 + tap;
        uint32_t wds[8];
        #pragma unroll
        for (int k = 0; k < 8; ++k) {
            uint32_t wd = 0;
            #pragma unroll
            for (int i = 0; i < 32; ++i) {
                float v = wp[(size_t)(k * 32 + i) * 9];
                wd |= (v >= 0.0f ? 1u : 0u) << i;
            }
            wds[k] = wd;
        }
        g_wpack[idx * 2 + 0] = make_uint4(wds[0], wds[1], wds[2], wds[3]);
        g_wpack[idx * 2 + 1] = make_uint4(wds[4], wds[5], wds[6], wds[7]);
    }
}

// carry-save adder: 2 LOP3; popc(a)+popc(b)+popc(d) == popc(s) + 2*popc(c)
#define CSA(s, c, a, b, d) do {                    \
    uint32_t _a = (a), _b = (b), _d = (d);         \
    (s) = _a ^ _b ^ _d;                            \
    (c) = (_a & _b) | (_a & _d) | (_b & _d);       \
} while (0)

// popcount-sum of 12 words via 5-CSA compression: 7 POPC instead of 12
__device__ __forceinline__ int csa_sum12(const uint32_t v[12]) {
    uint32_t s0, c0, s1, c1, s2, c2, s3, c3, s4, c4;
    CSA(s0, c0, v[0], v[1],  v[2]);
    CSA(s1, c1, v[3], v[4],  v[5]);
    CSA(s2, c2, v[6], v[7],  v[8]);
    CSA(s3, c3, v[9], v[10], v[11]);
    CSA(s4, c4, s0,   s1,    s2);
    int p1 = __popc(s4) + __popc(s3);
    int p2 = __popc(c0) + __popc(c1) + __popc(c2) + __popc(c3) + __popc(c4);
    return p1 + 2 * p2;
}

// ---------------- main conv: half cin split + CSA popc compression -----------
// Block = 256 threads = 8 warps. Lane = half*16 + csub.
//   csub (0..15) -> cout = bz*128 + wid*16 + csub;  half -> cin words 4h..4h+3.
// Block computes one (b, h) output row for 128 couts.
__global__ void __launch_bounds__(256, 3)
bconv_pop_kernel(const float* __restrict__ bias, float* __restrict__ out) {
    __shared__ uint4 xs[3 * WW_ * 2];     // [row][v][half]

    const int tid  = threadIdx.x;
    const int lane = tid & 31;
    const int wid  = tid >> 5;
    const int half = lane >> 4;
    const int csub = lane & 15;
    const int h    = blockIdx.x;
    const int b    = blockIdx.y;
    const int cout = blockIdx.z * 128 + wid * 16 + csub;

    const bool rv0 = (h > 0), rv2 = (h < HH_ - 1);

    // ---- stage x (3 rows x 56 cols x 2 halves), zero-fill invalid rows ----
    for (int i = tid; i < 3 * WW_ * 2; i += 256) {
        int row = i / (WW_ * 2);
        int rem = i - row * (WW_ * 2);
        int v = rem >> 1, j = rem & 1;
        int rin = h - 1 + row;
        uint4 val = make_uint4(0u, 0u, 0u, 0u);
        if (rin >= 0 && rin < HH_)
            val = g_xpack[((size_t)(b * HH_ + rin) * WW_ + v) * 2 + j];
        xs[(row * WW_ + v) * 2 + j] = val;
    }

    // ---- per-lane half-weights in registers (36 regs) ----
    uint32_t wreg[9][4];
    #pragma unroll
    for (int t = 0; t < 9; ++t) {
        uint4 a = g_wpack[(cout * 9 + t) * 2 + half];
        wreg[t][0] = a.x; wreg[t][1] = a.y; wreg[t][2] = a.z; wreg[t][3] = a.w;
    }
    const float bv = bias[cout];

    // ---- per-half pad-correction constants ----
    int pm[3], pl[3], pr[3];
    #pragma unroll
    for (int dh = 0; dh < 3; ++dh) {
        int p0 = 0, p1 = 0, p2 = 0;
        #pragma unroll
        for (int k = 0; k < 4; ++k) {
            p0 += __popc(wreg[dh * 3 + 0][k]);
            p1 += __popc(wreg[dh * 3 + 1][k]);
            p2 += __popc(wreg[dh * 3 + 2][k]);
        }
        pm[dh] = p0 + p1 + p2; pl[dh] = p1 + p2; pr[dh] = p0 + p1;
    }
    const int nrows = (int)rv0 + 1 + (int)rv2;
    const int cmid   = 384 * nrows + 2 * ((rv0 ? 0 : pm[0]) + (rv2 ? 0 : pm[2]));
    const int cleft  = 256 * nrows + 2 * ((rv0 ? 0 : pl[0]) + (rv2 ? 0 : pl[2]));
    const int cright = 256 * nrows + 2 * ((rv0 ? 0 : pr[0]) + (rv2 ? 0 : pr[2]));

    __syncthreads();

    float* obase = out + ((size_t)(b * COUT + cout) * HH_ + h) * WW_;

    int ring[4] = {0, 0, 0, 0};
    float fb[8];

    // v = input column. x col v feeds outputs w = v+1-dw, dw in {0,1,2}.
    for (int v0 = 0; v0 < 7; ++v0) {
        #pragma unroll
        for (int u = 0; u < 8; ++u) {
            const int v = v0 * 8 + u;

            // load 12 x words (3 rows x 4)
            uint32_t xw[12];
            #pragma unroll
            for (int row = 0; row < 3; ++row) {
                uint4 xa = xs[(row * WW_ + v) * 2 + half];
                xw[row * 4 + 0] = xa.x; xw[row * 4 + 1] = xa.y;
                xw[row * 4 + 2] = xa.z; xw[row * 4 + 3] = xa.w;
            }

            // per tap-column: 12 XOR + CSA-compressed popcount (7 POPC)
            #pragma unroll
            for (int j = 0; j < 3; ++j) {
                uint32_t vv[12];
                #pragma unroll
                for (int row = 0; row < 3; ++row) {
                    #pragma unroll
                    for (int k = 0; k < 4; ++k)
                        vv[row * 4 + k] = xw[row * 4 + k] ^ wreg[row * 3 + j][k];
                }
                int s = csa_sum12(vv);
                if (j == 0)      ring[(u + 1) & 3] += s;   // w = v+1
                else if (j == 1) ring[u & 3]       += s;   // w = v
                else             ring[(u + 3) & 3] += s;   // w = v-1 (completes)
            }

            if (u == 0) {
                if (v0 == 0) {
                    ring[3] = 0;            // discard w=-1 garbage
                } else {
                    int comb = cmid - 2 * ring[3];
                    comb += __shfl_xor_sync(0xffffffffu, comb, 16);
                    fb[7] = (float)comb + bv;
                    ring[3] = 0;
                    if (half == 0) {
                        *(float4*)(obase + (v0 - 1) * 8)     = make_float4(fb[0], fb[1], fb[2], fb[3]);
                        *(float4*)(obase + (v0 - 1) * 8 + 4) = make_float4(fb[4], fb[5], fb[6], fb[7]);
                    }
                }
            } else {
                const int slot = (u + 3) & 3;
                int c = cmid;
                if (u == 1) c = (v0 == 0) ? cleft : cmid;   // w==0 edge
                int comb = c - 2 * ring[slot];
                comb += __shfl_xor_sync(0xffffffffu, comb, 16);
                fb[(u - 1) & 7] = (float)comb + bv;
                ring[slot] = 0;
            }
        }
    }
    // tail: w = 55 (edge) sits in slot 3
    {
        int comb = cright - 2 * ring[3];
        comb += __shfl_xor_sync(0xffffffffu, comb, 16);
        fb[7] = (float)comb + bv;
    }
    if (half == 0) {
        *(float4*)(obase + 48) = make_float4(fb[0], fb[1], fb[2], fb[3]);
        *(float4*)(obase + 52) = make_float4(fb[4], fb[5], fb[6], fb[7]);
    }
}

// ---------------------------------------------------------------------------
extern "C" void kernel_launch(void* const* d_in, const int* in_sizes, int n_in,
                              void* d_out, int out_size) {
    const float* x    = (const float*)d_in[0];
    const float* wgt  = (const float*)d_in[1];
    const float* bias = (const float*)d_in[2];
    float* out = (float*)d_out;

    pack_all_kernel<<<401, 256>>>(x, wgt);
    dim3 grid(HH_, BATCH, 2);
    bconv_pop_kernel<<<grid, 256>>>(bias, out);
}

// round 17
// speedup vs baseline: 1.3174x; 1.0326x over previous
#include <cuda_runtime.h>
#include <cstdint>

#define BATCH 32
#define CIN   256
#define COUT  256
#define HH_   56
#define WW_   56
#define HW_   (HH_*WW_)
#define NPOS  (BATCH*HW_)

// ---------------- device scratch ----------------
__device__ uint4 g_xpack[NPOS * 2];        // [pos][2]: 8 u32 sign bits (bit=1 iff x>=0)
__device__ uint4 g_wpack[COUT * 9 * 2];    // [cout*9+tap][2]
__device__ int   g_one = 1;                // opaque 1 -> genuine IMAD on fma pipe
__device__ int   g_two = 2;                // opaque 2

// ---------------- fused pack kernel ----------------
__global__ void pack_all_kernel(const float* __restrict__ x,
                                const float* __restrict__ wgt) {
    if (blockIdx.x < 392) {                       // 392*256 == NPOS exactly
        int pos = blockIdx.x * 256 + threadIdx.x;
        int b  = pos / HW_;
        int hw = pos - b * HW_;
        const float* xp = x + (size_t)b * CIN * HW_ + hw;
        uint32_t wds[8];
        #pragma unroll
        for (int k = 0; k < 8; ++k) {
            uint32_t wd = 0;
            #pragma unroll
            for (int i = 0; i < 32; ++i) {
                float v = xp[(size_t)(k * 32 + i) * HW_];
                wd |= (v >= 0.0f ? 1u : 0u) << i;
            }
            wds[k] = wd;
        }
        g_xpack[pos * 2 + 0] = make_uint4(wds[0], wds[1], wds[2], wds[3]);
        g_xpack[pos * 2 + 1] = make_uint4(wds[4], wds[5], wds[6], wds[7]);
    } else {
        int idx = (blockIdx.x - 392) * 256 + threadIdx.x;   // cout*9+tap
        if (idx >= COUT * 9) return;
        int cout = idx / 9;
        int tap  = idx - cout * 9;
        const float* wp = wgt + (size_t)cout * CIN * 9 + tap;
        uint32_t wds[8];
        #pragma unroll
        for (int k = 0; k < 8; ++k) {
            uint32_t wd = 0;
            #pragma unroll
            for (int i = 0; i < 32; ++i) {
                float v = wp[(size_t)(k * 32 + i) * 9];
                wd |= (v >= 0.0f ? 1u : 0u) << i;
            }
            wds[k] = wd;
        }
        g_wpack[idx * 2 + 0] = make_uint4(wds[0], wds[1], wds[2], wds[3]);
        g_wpack[idx * 2 + 1] = make_uint4(wds[4], wds[5], wds[6], wds[7]);
    }
}

// carry-save adder: 2 LOP3; popc(a)+popc(b)+popc(d) == popc(s) + 2*popc(c)
#define CSA(s, c, a, b, d) do {                    \
    uint32_t _a = (a), _b = (b), _d = (d);         \
    (s) = _a ^ _b ^ _d;                            \
    (c) = (_a & _b) | (_a & _d) | (_b & _d);       \
} while (0)

// fma-pipe integer adds (one/two are runtime values)
#define PADD(d, a, b) \
    asm("mad.lo.s32 %0, %1, %2, %3;" : "=r"(d) : "r"(a), "r"(one), "r"(b))
#define PACC(acc, a) \
    asm("mad.lo.s32 %0, %1, %2, %0;" : "+r"(acc) : "r"(a), "r"(one))
#define PMAD2(d, a, b) /* d = 2*a + b */ \
    asm("mad.lo.s32 %0, %1, %2, %3;" : "=r"(d) : "r"(a), "r"(two), "r"(b))

// ---------------- main conv: half cin split + CSA + fma-pipe adds ------------
// Block = 256 threads = 8 warps. Lane = half*16 + csub.
//   csub (0..15) -> cout = bz*128 + wid*16 + csub;  half -> cin words 4h..4h+3.
__global__ void __launch_bounds__(256, 3)
bconv_pop_kernel(const float* __restrict__ bias, float* __restrict__ out) {
    __shared__ uint4 xs[3 * WW_ * 2];     // [row][v][half]

    const int tid  = threadIdx.x;
    const int lane = tid & 31;
    const int wid  = tid >> 5;
    const int half = lane >> 4;
    const int csub = lane & 15;
    const int h    = blockIdx.x;
    const int b    = blockIdx.y;
    const int cout = blockIdx.z * 128 + wid * 16 + csub;

    const bool rv0 = (h > 0), rv2 = (h < HH_ - 1);
    const int one = *(volatile int*)&g_one;
    const int two = *(volatile int*)&g_two;

    // ---- stage x (3 rows x 56 cols x 2 halves), zero-fill invalid rows ----
    for (int i = tid; i < 3 * WW_ * 2; i += 256) {
        int row = i / (WW_ * 2);
        int rem = i - row * (WW_ * 2);
        int v = rem >> 1, j = rem & 1;
        int rin = h - 1 + row;
        uint4 val = make_uint4(0u, 0u, 0u, 0u);
        if (rin >= 0 && rin < HH_)
            val = g_xpack[((size_t)(b * HH_ + rin) * WW_ + v) * 2 + j];
        xs[(row * WW_ + v) * 2 + j] = val;
    }

    // ---- per-lane half-weights in registers (36 regs) ----
    uint32_t wreg[9][4];
    #pragma unroll
    for (int t = 0; t < 9; ++t) {
        uint4 a = g_wpack[(cout * 9 + t) * 2 + half];
        wreg[t][0] = a.x; wreg[t][1] = a.y; wreg[t][2] = a.z; wreg[t][3] = a.w;
    }
    const float bv = bias[cout];

    // ---- per-half pad-correction constants ----
    int pm[3], pl[3], pr[3];
    #pragma unroll
    for (int dh = 0; dh < 3; ++dh) {
        int p0 = 0, p1 = 0, p2 = 0;
        #pragma unroll
        for (int k = 0; k < 4; ++k) {
            p0 += __popc(wreg[dh * 3 + 0][k]);
            p1 += __popc(wreg[dh * 3 + 1][k]);
            p2 += __popc(wreg[dh * 3 + 2][k]);
        }
        pm[dh] = p0 + p1 + p2; pl[dh] = p1 + p2; pr[dh] = p0 + p1;
    }
    const int nrows = (int)rv0 + 1 + (int)rv2;
    const int cmid   = 384 * nrows + 2 * ((rv0 ? 0 : pm[0]) + (rv2 ? 0 : pm[2]));
    const int cleft  = 256 * nrows + 2 * ((rv0 ? 0 : pl[0]) + (rv2 ? 0 : pl[2]));
    const int cright = 256 * nrows + 2 * ((rv0 ? 0 : pr[0]) + (rv2 ? 0 : pr[2]));

    __syncthreads();

    float* obase = out + ((size_t)(b * COUT + cout) * HH_ + h) * WW_;

    int ring[4] = {0, 0, 0, 0};
    float fb[8];

    // v = input column. x col v feeds outputs w = v+1-dw, dw in {0,1,2}.
    for (int v0 = 0; v0 < 7; ++v0) {
        #pragma unroll
        for (int u = 0; u < 8; ++u) {
            const int v = v0 * 8 + u;

            // load 12 x words (3 rows x 4)
            uint32_t xw[12];
            #pragma unroll
            for (int row = 0; row < 3; ++row) {
                uint4 xa = xs[(row * WW_ + v) * 2 + half];
                xw[row * 4 + 0] = xa.x; xw[row * 4 + 1] = xa.y;
                xw[row * 4 + 2] = xa.z; xw[row * 4 + 3] = xa.w;
            }

            // per tap-column: 12 XOR + 5 CSA (LOP3) + 7 POPC, adds on fma pipe
            #pragma unroll
            for (int j = 0; j < 3; ++j) {
                uint32_t vv[12];
                #pragma unroll
                for (int row = 0; row < 3; ++row) {
                    #pragma unroll
                    for (int k = 0; k < 4; ++k)
                        vv[row * 4 + k] = xw[row * 4 + k] ^ wreg[row * 3 + j][k];
                }
                uint32_t s0, c0, s1, c1, s2, c2, s3, c3, s4, c4;
                CSA(s0, c0, vv[0], vv[1],  vv[2]);
                CSA(s1, c1, vv[3], vv[4],  vv[5]);
                CSA(s2, c2, vv[6], vv[7],  vv[8]);
                CSA(s3, c3, vv[9], vv[10], vv[11]);
                CSA(s4, c4, s0,    s1,     s2);
                int p1; PADD(p1, __popc(s4), __popc(s3));
                int p2; PADD(p2, __popc(c0), __popc(c1));
                PACC(p2, __popc(c2));
                PACC(p2, __popc(c3));
                PACC(p2, __popc(c4));
                int s;  PMAD2(s, p2, p1);          // s = p1 + 2*p2
                if (j == 0)      PACC(ring[(u + 1) & 3], s);   // w = v+1
                else if (j == 1) PACC(ring[u & 3],       s);   // w = v
                else             PACC(ring[(u + 3) & 3], s);   // w = v-1
            }

            if (u == 0) {
                if (v0 == 0) {
                    ring[3] = 0;            // discard w=-1 garbage
                } else {
                    int comb = cmid - 2 * ring[3];
                    comb += __shfl_xor_sync(0xffffffffu, comb, 16);
                    fb[7] = (float)comb + bv;
                    ring[3] = 0;
                    if (half == 0) {
                        *(float4*)(obase + (v0 - 1) * 8)     = make_float4(fb[0], fb[1], fb[2], fb[3]);
                        *(float4*)(obase + (v0 - 1) * 8 + 4) = make_float4(fb[4], fb[5], fb[6], fb[7]);
                    }
                }
            } else {
                const int slot = (u + 3) & 3;
                int c = cmid;
                if (u == 1) c = (v0 == 0) ? cleft : cmid;   // w==0 edge
                int comb = c - 2 * ring[slot];
                comb += __shfl_xor_sync(0xffffffffu, comb, 16);
                fb[(u - 1) & 7] = (float)comb + bv;
                ring[slot] = 0;
            }
        }
    }
    // tail: w = 55 (edge) sits in slot 3
    {
        int comb = cright - 2 * ring[3];
        comb += __shfl_xor_sync(0xffffffffu, comb, 16);
        fb[7] = (float)comb + bv;
    }
    if (half == 0) {
        *(float4*)(obase + 48) = make_float4(fb[0], fb[1], fb[2], fb[3]);
        *(float4*)(obase + 52) = make_float4(fb[4], fb[5], fb[6], fb[7]);
    }
}

// ---------------------------------------------------------------------------
extern "C" void kernel_launch(void* const* d_in, const int* in_sizes, int n_in,
                              void* d_out, int out_size) {
    const float* x    = (const float*)d_in[0];
    const float* wgt  = (const float*)d_in[1];
    const float* bias = (const float*)d_in[2];
    float* out = (float*)d_out;

    pack_all_kernel<<<401, 256>>>(x, wgt);
    dim3 grid(HH_, BATCH, 2);
    bconv_pop_kernel<<<grid, 256>>>(bias, out);
}